// round 9
// baseline (speedup 1.0000x reference)
#include <cuda_runtime.h>
#include <math.h>

// B,H,L,D = 4,8,2048,64 ; FACTOR=5 -> sample_k = n_top = 40
#define Bq    4
#define Hq    8
#define Lq    2048
#define Dq    64
#define BH    (Bq*Hq)
#define SK    40
#define NT    40
#define NP    8            // K slices for k_M2
#define SL    (Lq/NP)      // 256 rows per slice
#define ZSP   4            // l-splits per (p,bh) in k_M2
#define ZL    (Lq/ZSP)     // 512 queries per z
#define LCAP  6144         // staged list capacity (avg need ~2560)
#define NCH   64           // cumsum chunks
#define CHLEN (Lq/NCH)     // 32
#define JS    8            // j-splits for AV
#define JT    (Lq/JS)      // 256
#define ST    128          // k_score j-tile
// dynamic smem for k_M2: K slice + offsets + staged list
#define SMEM_M2 (SL*Dq*4 + (ZL+1+3)*4 + LCAP*4)

// ---- device scratch (no allocations allowed) ----
__device__ int    g_cnt[NP][Lq];
__device__ int    g_off[NP][Lq+1];     // GLOBAL offsets into g_list
__device__ int    g_list[Lq*SK];       // per-slice, sorted-by-query sample lists
__device__ float2 g_part2[NP*BH*Lq];   // per-slice (max,sum) partials
__device__ int    g_top[BH*NT];
__device__ int    g_sel[BH*Lq];        // row -> u (or -1)
__device__ float  g_S[(size_t)BH*NT*Lq];   // exp(scores) (10.5MB)
__device__ float  g_den[BH*NT];        // softmax denominators (atomic)
__device__ float  g_part[BH*JS*NT*Dq]; // AV partials
__device__ float  g_csum[BH*NCH*Dq];

// ---------------------------------------------------------------------------
// Prep 1: per-query per-slice sample counts (packed byte counters); zero g_den.
// ---------------------------------------------------------------------------
__global__ void k_cnt(const int* __restrict__ I) {
    int l = blockIdx.x*256 + threadIdx.x;          // grid 8
    if (l < BH*NT) g_den[l] = 0.f;
    unsigned lo = 0, hi = 0;
    const int* r = I + l*SK;
    #pragma unroll
    for (int s = 0; s < SK; ++s) {
        int p = r[s] >> 8;                          // slice of 256
        unsigned inc = 1u << ((p & 3)*8);
        if (p < 4) lo += inc; else hi += inc;
    }
    #pragma unroll
    for (int p = 0; p < 4; ++p) g_cnt[p][l]   = (lo >> (p*8)) & 255;
    #pragma unroll
    for (int p = 0; p < 4; ++p) g_cnt[p+4][l] = (hi >> (p*8)) & 255;
}

// Prep 2: exclusive prefix -> global offsets (single block, warp-parallel scan)
__global__ void k_scan() {
    __shared__ int wsum[8];
    __shared__ int s_tot;
    int tid = threadIdx.x, lane = tid & 31, wid = tid >> 5;
    int base = 0;
    for (int p = 0; p < NP; ++p) {
        int loc[8]; int s = 0;
        #pragma unroll
        for (int k = 0; k < 8; ++k) { loc[k] = s; s += g_cnt[p][tid*8+k]; }
        int v = s;
        #pragma unroll
        for (int o = 1; o < 32; o <<= 1) {
            int t = __shfl_up_sync(0xffffffffu, v, o);
            if (lane >= o) v += t;
        }
        if (lane == 31) wsum[wid] = v;
        __syncthreads();
        if (tid == 0) {
            int a = 0;
            #pragma unroll
            for (int i = 0; i < 8; ++i) { int t = wsum[i]; wsum[i] = a; a += t; }
            s_tot = a;
        }
        __syncthreads();
        int excl = v - s + wsum[wid];
        #pragma unroll
        for (int k = 0; k < 8; ++k) g_off[p][tid*8+k] = base + excl + loc[k];
        if (tid == 255) g_off[p][Lq] = base + excl + s;
        base += s_tot;
        __syncthreads();
    }
}

// Prep 3: fill lists (stores local row index within slice)
__global__ void k_fill(const int* __restrict__ I) {
    int l = blockIdx.x*256 + threadIdx.x;          // grid 8
    int o0=g_off[0][l], o1=g_off[1][l], o2=g_off[2][l], o3=g_off[3][l];
    int o4=g_off[4][l], o5=g_off[5][l], o6=g_off[6][l], o7=g_off[7][l];
    const int* r = I + l*SK;
    #pragma unroll
    for (int s = 0; s < SK; ++s) {
        int j = r[s];
        int p = j >> 8, jj = j & (SL-1);
        if (p < 4) {
            if (p < 2) { if (p == 0) g_list[o0++] = jj; else g_list[o1++] = jj; }
            else       { if (p == 2) g_list[o2++] = jj; else g_list[o3++] = jj; }
        } else {
            if (p < 6) { if (p == 4) g_list[o4++] = jj; else g_list[o5++] = jj; }
            else       { if (p == 6) g_list[o6++] = jj; else g_list[o7++] = jj; }
        }
    }
}

// ---------------------------------------------------------------------------
// k_M2: block (slice p, bh, z). K slice (256x64, 64KB) + list segment staged
// in smem. 92KB/CTA -> 2 CTAs/SM (100% occ). Warp per query, 8-lane dot
// groups (4 samples/iter), 3 shfl per group-dot. Register-dieted.
// ---------------------------------------------------------------------------
__global__ void __launch_bounds__(1024, 2) k_M2(const float* __restrict__ Q,
                                                const float* __restrict__ K) {
    extern __shared__ float ks[];                  // SL*Dq floats (64KB)
    float4* ks4 = (float4*)ks;
    int* so = (int*)(ks + SL*Dq);                  // ZL+1 local offsets
    int* sls = so + (ZL+1+3);                      // staged list (LCAP)
    int p = blockIdx.x, bh = blockIdx.y, z = blockIdx.z;
    int tid = threadIdx.x, warp = tid >> 5, lane = tid & 31;
    int g = lane >> 3, e = lane & 7;
    int zl0 = z*ZL;

    const float4* Ks = (const float4*)(K + ((size_t)bh*Lq + (size_t)p*SL)*Dq);
    for (int i = tid; i < SL*(Dq/4); i += 1024) ks4[i] = Ks[i];

    int sbeg = g_off[p][zl0];
    int seglen = g_off[p][zl0 + ZL] - sbeg;
    for (int i = tid; i <= ZL; i += 1024) so[i] = g_off[p][zl0 + i] - sbeg;
    const int* lp;
    if (seglen <= LCAP) {                          // uniform per block
        for (int i = tid; i < seglen; i += 1024) sls[i] = g_list[sbeg + i];
        lp = sls;
    } else {
        lp = g_list + sbeg;                        // fallback (never in practice)
    }
    __syncthreads();

    const float4* Q4 = (const float4*)Q;
    #pragma unroll 1
    for (int i = 0; i < ZL/32; ++i) {
        int ll = warp + 32*i;
        int l  = zl0 + ll;
        int c = so[ll], end = so[ll+1];
        float mx = -INFINITY, sm = 0.f;
        if (c < end) {
            size_t qr = ((size_t)bh*Lq + l)*16;
            float4 q0 = Q4[qr + e], q1 = Q4[qr + e + 8];
            #pragma unroll 1
            for (; c < end; c += 4) {
                int idx = c + g;
                bool v = idx < end;
                int j = lp[v ? idx : c];
                const float4* kb = ks4 + (j << 4);
                float4 x = kb[e], y = kb[e + 8];
                float pr = q0.x*x.x + q0.y*x.y + q0.z*x.z + q0.w*x.w
                         + q1.x*y.x + q1.y*y.y + q1.z*y.z + q1.w*y.w;
                pr += __shfl_xor_sync(0xffffffffu, pr, 1);
                pr += __shfl_xor_sync(0xffffffffu, pr, 2);
                pr += __shfl_xor_sync(0xffffffffu, pr, 4);
                if (v) { mx = fmaxf(mx, pr); sm += pr; }
            }
            mx = fmaxf(mx, __shfl_xor_sync(0xffffffffu, mx, 8));
            mx = fmaxf(mx, __shfl_xor_sync(0xffffffffu, mx, 16));
            sm += __shfl_xor_sync(0xffffffffu, sm, 8);
            sm += __shfl_xor_sync(0xffffffffu, sm, 16);
        }
        if (lane == 0) g_part2[((size_t)p*BH + bh)*Lq + l] = make_float2(mx, sm);
    }
}

// ---------------------------------------------------------------------------
// k_topk: radix-select of the top-40 M values (exact threshold, lowest-index
// tie-break = jax top_k). Output order arbitrary (u<->row bijection consistent).
// ---------------------------------------------------------------------------
__global__ void k_topk() {
    int bh = blockIdx.x, tid = threadIdx.x;
    __shared__ unsigned keys[Lq];
    __shared__ int hist[256];
    __shared__ int tie[Lq];
    __shared__ int tops[NT];
    __shared__ int s_d, s_acc, s_ngt, s_ntie;

    for (int i = tid; i < Lq; i += 256) {
        float mx = -INFINITY, sm = 0.f;
        #pragma unroll
        for (int p = 0; p < NP; ++p) {
            float2 v = g_part2[((size_t)p*BH + bh)*Lq + i];
            mx = fmaxf(mx, v.x); sm += v.y;
        }
        float m = mx - sm * (1.0f/(float)Lq);
        unsigned u = __float_as_uint(m);
        keys[i] = (u & 0x80000000u) ? ~u : (u | 0x80000000u);
    }
    if (tid == 0) { s_ngt = 0; s_ntie = 0; }
    __syncthreads();

    unsigned prefix = 0; int k = NT;
    #pragma unroll
    for (int level = 3; level >= 0; --level) {
        int sh = level*8;
        hist[tid] = 0;
        __syncthreads();
        unsigned maskAbove = (level==3) ? 0u : (0xFFFFFFFFu << (sh+8));
        for (int i = tid; i < Lq; i += 256) {
            unsigned key = keys[i];
            if ((key & maskAbove) == prefix)
                atomicAdd(&hist[(key >> sh) & 255], 1);
        }
        __syncthreads();
        if (tid == 0) {
            int acc = 0, d = 255;
            for (; d > 0; --d) { if (acc + hist[d] >= k) break; acc += hist[d]; }
            s_d = d; s_acc = acc;
        }
        __syncthreads();
        k -= s_acc;
        prefix |= ((unsigned)s_d) << sh;
        __syncthreads();
    }
    unsigned T = prefix;

    for (int i = tid; i < Lq; i += 256) {
        unsigned key = keys[i];
        if (key > T)       { int pos = atomicAdd(&s_ngt, 1);  tops[pos] = i; }
        else if (key == T) { int pos = atomicAdd(&s_ntie, 1); tie[pos]  = i; }
    }
    __syncthreads();
    int ngt = s_ngt, ntie = s_ntie;
    if (tid < 32) {
        for (int t = 0; t < k; ++t) {
            long long best = 0x7FFFFFFFFFFFFFFFLL;
            for (int i = tid; i < ntie; i += 32) {
                long long c = ((long long)tie[i] << 32) | (unsigned)i;
                if (c < best) best = c;
            }
            #pragma unroll
            for (int o = 16; o; o >>= 1) {
                long long c = __shfl_xor_sync(0xffffffffu, best, o);
                if (c < best) best = c;
            }
            if (tid == 0) {
                int slot = (int)(best & 0xffffffffu);
                tops[ngt + t] = (int)(best >> 32);
                tie[slot] = 0x7FFFFFFF;
            }
            __syncwarp();
        }
    }
    __syncthreads();

    for (int i = tid; i < Lq; i += 256) g_sel[bh*Lq + i] = -1;
    if (tid < NT) g_top[bh*NT + tid] = tops[tid];
    __syncthreads();
    if (tid < NT) g_sel[bh*Lq + tops[tid]] = tid;
}

// ---------------------------------------------------------------------------
// k_score: P[bh][u][j] = exp(scale*Qr[u].K[j]) (0 masked). Block-uniform
// early-out for fully-masked u-tiles. Row denominators via shfl+atomics.
// ---------------------------------------------------------------------------
__global__ void __launch_bounds__(256) k_score(const float* __restrict__ Q,
                                               const float* __restrict__ K) {
    __shared__ float4 qs4[NT*16];       // Qr gathered, 10.25KB
    __shared__ int    mtop[NT];
    __shared__ float  kt[ST*65];        // padded K tile, 33.3KB
    __shared__ float  dsum[NT];

    int jt0 = blockIdx.x * ST, bh = blockIdx.y;
    int tid = threadIdx.x, lane = tid & 31;
    int j = tid & (ST-1), half = tid >> 7;     // 128 j x 2 u-halves

    if (tid < NT) { mtop[tid] = g_top[bh*NT + tid]; dsum[tid] = 0.f; }
    __syncthreads();

    const float4* Q4 = (const float4*)Q;
    for (int i = tid; i < NT*16; i += 256) {
        int u = i >> 4, d4 = i & 15;
        qs4[i] = Q4[((size_t)bh*Lq + mtop[u])*16 + d4];
    }
    const float4* K4 = (const float4*)K;
    for (int i = tid; i < ST*16; i += 256) {
        int r = i >> 4, c4 = i & 15;
        float4 v = K4[((size_t)bh*Lq + jt0 + r)*16 + c4];
        kt[r*65 + c4*4+0] = v.x; kt[r*65 + c4*4+1] = v.y;
        kt[r*65 + c4*4+2] = v.z; kt[r*65 + c4*4+3] = v.w;
    }
    __syncthreads();

    float kr[Dq];
    #pragma unroll
    for (int d = 0; d < Dq; ++d) kr[d] = kt[j*65 + d];

    int jg = jt0 + j;
    int u0 = half * 20;
    float* Sout = g_S + ((size_t)bh*NT)*Lq + jg;
    #pragma unroll 1
    for (int u = u0; u < u0 + 20; ++u) {
        int m = mtop[u];
        if (jt0 > m) {                   // block-uniform: whole tile masked
            Sout[(size_t)u*Lq] = 0.f;
            continue;
        }
        float s = 0.f;
        #pragma unroll
        for (int d4 = 0; d4 < 16; ++d4) {
            float4 qv = qs4[u*16 + d4];
            s += kr[d4*4+0]*qv.x + kr[d4*4+1]*qv.y + kr[d4*4+2]*qv.z + kr[d4*4+3]*qv.w;
        }
        float e = (jg > m) ? 0.f : __expf(s * 0.125f);
        Sout[(size_t)u*Lq] = e;
        float v = e;
        v += __shfl_xor_sync(0xffffffffu, v, 1);
        v += __shfl_xor_sync(0xffffffffu, v, 2);
        v += __shfl_xor_sync(0xffffffffu, v, 4);
        v += __shfl_xor_sync(0xffffffffu, v, 8);
        v += __shfl_xor_sync(0xffffffffu, v, 16);
        if (lane == 0) atomicAdd(&dsum[u], v);
    }
    __syncthreads();
    if (tid < NT) atomicAdd(&g_den[bh*NT + tid], dsum[tid]);
}

// ---------------------------------------------------------------------------
// k_av: partial AV per (jsplit,bh). p-tile (40x256) in smem, V coalesced.
// ---------------------------------------------------------------------------
__global__ void __launch_bounds__(256) k_av(const float* __restrict__ V) {
    __shared__ float4 ps4[NT*64];       // 40KB
    int js = blockIdx.x, bh = blockIdx.y;
    int tid = threadIdx.x, d = tid & 63, ug = tid >> 6;
    int j0 = js * JT;

    const float4* S4 = (const float4*)(g_S + ((size_t)bh*NT)*Lq);
    for (int i = tid; i < NT*64; i += 256) {
        int u = i >> 6, j4 = i & 63;
        ps4[i] = S4[((size_t)u*Lq + j0)/4 + j4];
    }
    __syncthreads();

    const float* Vb = V + ((size_t)bh*Lq + j0)*Dq + d;
    float acc[10];
    #pragma unroll
    for (int k = 0; k < 10; ++k) acc[k] = 0.f;

    for (int j4 = 0; j4 < 64; ++j4) {
        float v0 = Vb[(size_t)(j4*4+0)*Dq], v1 = Vb[(size_t)(j4*4+1)*Dq];
        float v2 = Vb[(size_t)(j4*4+2)*Dq], v3 = Vb[(size_t)(j4*4+3)*Dq];
        #pragma unroll
        for (int k = 0; k < 10; ++k) {
            float4 pv = ps4[(ug*10 + k)*64 + j4];
            acc[k] += pv.x*v0 + pv.y*v1 + pv.z*v2 + pv.w*v3;
        }
    }
    #pragma unroll
    for (int k = 0; k < 10; ++k)
        g_part[(((size_t)bh*JS + js)*NT + ug*10 + k)*Dq + d] = acc[k];
}

// ---------------------------------------------------------------------------
// cumsum: chunk sums -> chunk prefix -> output with fused combine+scatter.
// ---------------------------------------------------------------------------
__global__ void k_csum1(const float* __restrict__ V) {
    int bh = blockIdx.y;
    int ch = blockIdx.x*4 + (threadIdx.x >> 6);
    int d  = threadIdx.x & 63;
    const float* v = V + ((size_t)bh*Lq + ch*CHLEN)*Dq + d;
    float a = 0.f;
    #pragma unroll
    for (int l = 0; l < CHLEN; l += 4) {
        float x0 = v[(size_t)l*Dq],     x1 = v[(size_t)(l+1)*Dq];
        float x2 = v[(size_t)(l+2)*Dq], x3 = v[(size_t)(l+3)*Dq];
        a += (x0+x1) + (x2+x3);
    }
    g_csum[(bh*NCH + ch)*Dq + d] = a;
}

__global__ void k_csum2() {
    int t = blockIdx.x*256 + threadIdx.x;   // BH*Dq = 2048
    int bh = t >> 6, d = t & 63;
    float a = 0.f;
    #pragma unroll
    for (int ch = 0; ch < NCH; ++ch) {
        int off = (bh*NCH + ch)*Dq + d;
        float s = g_csum[off];
        g_csum[off] = a;
        a += s;
    }
}

__global__ void k_csum3(const float* __restrict__ V, float* __restrict__ O) {
    int bh = blockIdx.y;
    int ch = blockIdx.x*4 + (threadIdx.x >> 6);
    int d  = threadIdx.x & 63;
    int l0 = ch*CHLEN;
    size_t base = ((size_t)bh*Lq + l0)*Dq + d;
    float a = g_csum[(bh*NCH + ch)*Dq + d];
    const int* sel = g_sel + bh*Lq + l0;
    #pragma unroll 4
    for (int l = 0; l < CHLEN; ++l) {
        a += V[base + (size_t)l*Dq];
        float out = a;
        int s = sel[l];
        if (s >= 0) {
            float acc8 = 0.f;
            #pragma unroll
            for (int js = 0; js < JS; ++js)
                acc8 += g_part[(((size_t)bh*JS + js)*NT + s)*Dq + d];
            out = acc8 / g_den[bh*NT + s];
        }
        O[base + (size_t)l*Dq] = out;
    }
}

extern "C" void kernel_launch(void* const* d_in, const int* in_sizes, int n_in,
                              void* d_out, int out_size) {
    const float* Q = (const float*)d_in[0];
    const float* K = (const float*)d_in[1];
    const float* V = (const float*)d_in[2];
    const int*   I = (const int*)  d_in[3];
    float* O = (float*)d_out;

    cudaFuncSetAttribute(k_M2, cudaFuncAttributeMaxDynamicSharedMemorySize, SMEM_M2);

    k_cnt  <<<Lq/256, 256>>>(I);
    k_scan <<<1, 256>>>();
    k_fill <<<Lq/256, 256>>>(I);
    k_M2   <<<dim3(NP, BH, ZSP), 1024, SMEM_M2>>>(Q, K);
    k_topk <<<BH, 256>>>();
    k_score<<<dim3(Lq/ST, BH), 256>>>(Q, K);
    k_av   <<<dim3(JS, BH), 256>>>(V);
    k_csum1<<<dim3(NCH/4, BH), 256>>>(V);
    k_csum2<<<BH*Dq/256, 256>>>();
    k_csum3<<<dim3(NCH/4, BH), 256>>>(V, O);
}